// round 5
// baseline (speedup 1.0000x reference)
#include <cuda_runtime.h>
#include <cstdint>

#define N 8192

// ---------------- device scratch (no allocations allowed) ----------------
__device__ float g_xmT[64 * N];   // built query features, transposed [64][N]
__device__ float g_xvT[96 * N];   // [96][N]
__device__ float g_XmT[64 * N];   // X_mean transposed
__device__ float g_XvT[96 * N];   // X_var transposed
__device__ float g_qn_mean[N];    // ||x_mean row||^2
__device__ float g_qn_var[N];
__device__ float g_Xn_mean[N];    // ||X_mean row||^2
__device__ float g_Xn_var[N];
__device__ float g_Lmean[N * 32]; // Lambda_mean
__device__ float g_Lvar[N * 32];  // Lambda_var

// ---------------- zero Lambda accumulators ----------------
__global__ void zero_L_kernel() {
    int i = blockIdx.x * blockDim.x + threadIdx.x;
    const int total = N * 32;
    for (; i < total; i += gridDim.x * blockDim.x) {
        g_Lmean[i] = 0.0f;
        g_Lvar[i]  = 0.0f;
    }
}

// ---------------- build query features (transposed) + norms + seed output ----------------
// x_mean = [x_mu, y_mean+y_var]            (64)
// x_var  = [x_mu, 0.01*flip(y_eta), y_mean+y_var] (96)
// out    = y_mean + y_var   (z terms added later via atomicAdd)
__global__ __launch_bounds__(256) void build_queries_kernel(
    const float* __restrict__ x_mu, const float* __restrict__ y_eta,
    const float* __restrict__ y_mean, const float* __restrict__ y_var,
    float* __restrict__ out)
{
    __shared__ float sa[32][33];
    __shared__ float se[32][33];
    __shared__ float ss[32][33];
    int q0   = blockIdx.x * 32;
    int tid  = threadIdx.x;
    int lane = tid & 31;
    int w    = tid >> 5;

#pragma unroll
    for (int rr = 0; rr < 4; rr++) {
        int qr = w + rr * 8;
        int q  = q0 + qr;
        float a = x_mu[q * 32 + lane];
        float s = y_mean[q * 32 + lane] + y_var[q * 32 + lane];
        float e = 0.01f * y_eta[(N - 1 - q) * 32 + lane];
        sa[qr][lane] = a;
        se[qr][lane] = e;
        ss[qr][lane] = s;
        out[q * 32 + lane] = s;
        float nm = a * a + s * s;
        float nv = nm + e * e;
#pragma unroll
        for (int o = 16; o > 0; o >>= 1) {
            nm += __shfl_xor_sync(0xffffffffu, nm, o);
            nv += __shfl_xor_sync(0xffffffffu, nv, o);
        }
        if (lane == 0) { g_qn_mean[q] = nm; g_qn_var[q] = nv; }
    }
    __syncthreads();
    // transposed writes: coalesced over q
    for (int idx = tid; idx < 64 * 32; idx += 256) {
        int k = idx >> 5, c = idx & 31;
        float v = (k < 32) ? sa[c][k] : ss[c][k - 32];
        g_xmT[k * N + q0 + c] = v;
    }
    for (int idx = tid; idx < 96 * 32; idx += 256) {
        int k = idx >> 5, c = idx & 31;
        float v = (k < 32) ? sa[c][k] : ((k < 64) ? se[c][k - 32] : ss[c][k - 64]);
        g_xvT[k * N + q0 + c] = v;
    }
}

// ---------------- transpose X + row norms ----------------
template <int D, int V>
__global__ __launch_bounds__(256) void transpose_norm_kernel(const float* __restrict__ X)
{
    float* XT = V ? g_XvT : g_XmT;
    float* n2 = V ? g_Xn_var : g_Xn_mean;
    __shared__ float s[32][D + 1];
    int q0  = blockIdx.x * 32;
    int tid = threadIdx.x;
    for (int idx = tid; idx < 32 * D; idx += 256) {
        int r = idx / D, c = idx - r * D;
        s[r][c] = X[(q0 + r) * D + c];
    }
    __syncthreads();
    if (tid < 32) {
        float acc = 0.0f;
#pragma unroll 8
        for (int k = 0; k < D; k++) { float v = s[tid][k]; acc = fmaf(v, v, acc); }
        n2[q0 + tid] = acc;
    }
    for (int idx = tid; idx < D * 32; idx += 256) {
        int k = idx >> 5, c = idx & 31;
        XT[k * N + q0 + c] = s[c][k];
    }
}

// ---------------- Lambda = kXX_inv @ Z   ([N][N] @ [N][32]) ----------------
// grid (32 row-blocks of 256 rows, 8 k-splits), block 256, thread tile 4 rows x 8 cols
template <int V>
__global__ __launch_bounds__(256) void lambda_gemm_kernel(
    const float* __restrict__ A, const float* __restrict__ B)
{
    float* C = V ? g_Lvar : g_Lmean;
    __shared__ float sA[256][20];
    __shared__ float sB[16][36];
    int tid   = threadIdx.x;
    int r0    = blockIdx.x * 256;
    int kbase = blockIdx.y * (N / 8);
    int tx = tid & 3;        // col group: 8 cols
    int ty = tid >> 2;       // 0..63: rows ty*4..+3

    float acc[4][8];
#pragma unroll
    for (int i = 0; i < 4; i++)
#pragma unroll
        for (int j = 0; j < 8; j++) acc[i][j] = 0.0f;

    for (int kc = kbase; kc < kbase + N / 8; kc += 16) {
#pragma unroll
        for (int i = 0; i < 4; i++) {
            int f   = tid + 256 * i;
            int row = f >> 2;
            int kq  = (f & 3) << 2;
            float4 v = *reinterpret_cast<const float4*>(&A[(size_t)(r0 + row) * N + kc + kq]);
            *reinterpret_cast<float4*>(&sA[row][kq]) = v;
        }
        if (tid < 128) {
            int k = tid >> 3, jq = (tid & 7) << 2;
            *reinterpret_cast<float4*>(&sB[k][jq]) =
                *reinterpret_cast<const float4*>(&B[(kc + k) * 32 + jq]);
        }
        __syncthreads();
#pragma unroll
        for (int k = 0; k < 16; k++) {
            float4 b0 = *reinterpret_cast<const float4*>(&sB[k][tx * 8]);
            float4 b1 = *reinterpret_cast<const float4*>(&sB[k][tx * 8 + 4]);
#pragma unroll
            for (int i = 0; i < 4; i++) {
                float a = sA[ty * 4 + i][k];
                acc[i][0] = fmaf(a, b0.x, acc[i][0]);
                acc[i][1] = fmaf(a, b0.y, acc[i][1]);
                acc[i][2] = fmaf(a, b0.z, acc[i][2]);
                acc[i][3] = fmaf(a, b0.w, acc[i][3]);
                acc[i][4] = fmaf(a, b1.x, acc[i][4]);
                acc[i][5] = fmaf(a, b1.y, acc[i][5]);
                acc[i][6] = fmaf(a, b1.z, acc[i][6]);
                acc[i][7] = fmaf(a, b1.w, acc[i][7]);
            }
        }
        __syncthreads();
    }
#pragma unroll
    for (int i = 0; i < 4; i++)
#pragma unroll
        for (int j = 0; j < 8; j++)
            atomicAdd(&C[(size_t)(r0 + ty * 4 + i) * 32 + tx * 8 + j], acc[i][j]);
}

// ---------------- fused RBF + z gemm ----------------
// z[q][:] += sum_n exp(min(2*dot - ||X_n||^2 - ||x_q||^2, 0)/128) * Lambda[n][:]
// grid (128 q-tiles of 64, 2 n-splits of 4096), block 256
template <int D, int V>
__global__ __launch_bounds__(256) void fused_rbf_kernel(float* __restrict__ out)
{
    const float* XT  = V ? g_XvT     : g_XmT;
    const float* qT  = V ? g_xvT     : g_xmT;
    const float* Xn2 = V ? g_Xn_var  : g_Xn_mean;
    const float* qn2 = V ? g_qn_var  : g_qn_mean;
    const float* Lam = V ? g_Lvar    : g_Lmean;

    extern __shared__ float sm[];
    float* sq  = sm;              // [D][68]
    float* sX  = sq + D * 68;     // [D][68]
    float* sK  = sX + D * 68;     // [64][68]
    float* sL  = sK + 64 * 68;    // [64][36]
    float* sXn = sL + 64 * 36;    // [64]
    float* sqn = sXn + 64;        // [64]

    int tid    = threadIdx.x;
    int q0     = blockIdx.x * 64;
    int n0base = blockIdx.y * (N / 2);

    for (int idx = tid; idx < D * 64; idx += 256) {
        int k = idx >> 6, c = idx & 63;
        sq[k * 68 + c] = qT[k * N + q0 + c];
    }
    if (tid < 64) sqn[tid] = qn2[q0 + tid];

    float z[8];
#pragma unroll
    for (int i = 0; i < 8; i++) z[i] = 0.0f;

    int qs = tid >> 4;   // 0..15 (S-phase q group of 4)
    int ns = tid & 15;   // 0..15 (S-phase n group of 4)
    int qz = tid >> 5;   // 0..7  (z-phase q group of 8)
    int j  = tid & 31;   // z-phase output column

    for (int n0 = n0base; n0 < n0base + N / 2; n0 += 64) {
        __syncthreads();
        for (int idx = tid; idx < D * 64; idx += 256) {
            int k = idx >> 6, c = idx & 63;
            sX[k * 68 + c] = XT[k * N + n0 + c];
        }
        for (int idx = tid; idx < 512; idx += 256) {
            int n = idx >> 3, jq = (idx & 7) << 2;
            *reinterpret_cast<float4*>(&sL[n * 36 + jq]) =
                *reinterpret_cast<const float4*>(&Lam[(n0 + n) * 32 + jq]);
        }
        if (tid < 64) sXn[tid] = Xn2[n0 + tid];
        __syncthreads();

        // S phase: 4x4 dots
        float s[4][4];
#pragma unroll
        for (int i = 0; i < 4; i++)
#pragma unroll
            for (int jj = 0; jj < 4; jj++) s[i][jj] = 0.0f;

#pragma unroll 4
        for (int k = 0; k < D; k++) {
            float4 xa = *reinterpret_cast<const float4*>(&sX[k * 68 + ns * 4]);
            float4 qa = *reinterpret_cast<const float4*>(&sq[k * 68 + qs * 4]);
            float xv[4] = {xa.x, xa.y, xa.z, xa.w};
            float qv[4] = {qa.x, qa.y, qa.z, qa.w};
#pragma unroll
            for (int i = 0; i < 4; i++)
#pragma unroll
                for (int jj = 0; jj < 4; jj++)
                    s[i][jj] = fmaf(xv[i], qv[jj], s[i][jj]);
        }
        // exp + write K tile
#pragma unroll
        for (int i = 0; i < 4; i++) {
            float xn = sXn[ns * 4 + i];
            float4 kv;
            kv.x = __expf(fminf(fmaf(2.0f, s[i][0], -(xn + sqn[qs * 4 + 0])), 0.0f) * 0.0078125f);
            kv.y = __expf(fminf(fmaf(2.0f, s[i][1], -(xn + sqn[qs * 4 + 1])), 0.0f) * 0.0078125f);
            kv.z = __expf(fminf(fmaf(2.0f, s[i][2], -(xn + sqn[qs * 4 + 2])), 0.0f) * 0.0078125f);
            kv.w = __expf(fminf(fmaf(2.0f, s[i][3], -(xn + sqn[qs * 4 + 3])), 0.0f) * 0.0078125f);
            *reinterpret_cast<float4*>(&sK[(ns * 4 + i) * 68 + qs * 4]) = kv;
        }
        __syncthreads();

        // z phase: z[q][j] += K[n][q] * Lam[n][j]
#pragma unroll 4
        for (int n = 0; n < 64; n++) {
            float lam = sL[n * 36 + j];
            float4 k0 = *reinterpret_cast<const float4*>(&sK[n * 68 + qz * 8]);
            float4 k1 = *reinterpret_cast<const float4*>(&sK[n * 68 + qz * 8 + 4]);
            z[0] = fmaf(k0.x, lam, z[0]);
            z[1] = fmaf(k0.y, lam, z[1]);
            z[2] = fmaf(k0.z, lam, z[2]);
            z[3] = fmaf(k0.w, lam, z[3]);
            z[4] = fmaf(k1.x, lam, z[4]);
            z[5] = fmaf(k1.y, lam, z[5]);
            z[6] = fmaf(k1.z, lam, z[6]);
            z[7] = fmaf(k1.w, lam, z[7]);
        }
    }
#pragma unroll
    for (int i = 0; i < 8; i++)
        atomicAdd(&out[(q0 + qz * 8 + i) * 32 + j], z[i]);
}

// ---------------- launch ----------------
extern "C" void kernel_launch(void* const* d_in, const int* in_sizes, int n_in,
                              void* d_out, int out_size)
{
    const float* x_mu        = (const float*)d_in[0];
    const float* y_eta       = (const float*)d_in[1];
    const float* y_mean      = (const float*)d_in[2];
    const float* y_var       = (const float*)d_in[3];
    const float* X_mean      = (const float*)d_in[4];
    const float* X_var       = (const float*)d_in[5];
    const float* Z_mean      = (const float*)d_in[6];
    const float* Z_var       = (const float*)d_in[7];
    const float* kXXmean_inv = (const float*)d_in[8];
    const float* kXXvar_inv  = (const float*)d_in[9];
    float* out = (float*)d_out;

    const int SM64 = (2 * 64 * 68 + 64 * 68 + 64 * 36 + 128) * (int)sizeof(float);
    const int SM96 = (2 * 96 * 68 + 64 * 68 + 64 * 36 + 128) * (int)sizeof(float);
    cudaFuncSetAttribute(fused_rbf_kernel<64, 0>,
                         cudaFuncAttributeMaxDynamicSharedMemorySize, SM64);
    cudaFuncSetAttribute(fused_rbf_kernel<96, 1>,
                         cudaFuncAttributeMaxDynamicSharedMemorySize, SM96);

    zero_L_kernel<<<256, 256>>>();
    build_queries_kernel<<<256, 256>>>(x_mu, y_eta, y_mean, y_var, out);
    transpose_norm_kernel<64, 0><<<256, 256>>>(X_mean);
    transpose_norm_kernel<96, 1><<<256, 256>>>(X_var);

    lambda_gemm_kernel<0><<<dim3(32, 8), 256>>>(kXXmean_inv, Z_mean);
    lambda_gemm_kernel<1><<<dim3(32, 8), 256>>>(kXXvar_inv, Z_var);

    fused_rbf_kernel<64, 0><<<dim3(128, 2), 256, SM64>>>(out);
    fused_rbf_kernel<96, 1><<<dim3(128, 2), 256, SM96>>>(out);
}

// round 7
// speedup vs baseline: 2.7607x; 2.7607x over previous
#include <cuda_runtime.h>
#include <cstdint>

#define NQ 8192

__device__ float g_qm[NQ * 64];
__device__ float g_qv[NQ * 96];
__device__ float g_eqm[NQ], g_eqv[NQ], g_exnm[NQ], g_exnv[NQ];
__device__ float g_L[2][NQ * 32];

__device__ __forceinline__ uint32_t sm_u32(const void* p) {
    uint32_t a;
    asm("{ .reg .u64 t; cvta.to.shared.u64 t, %1; cvt.u32.u64 %0, t; }" : "=r"(a) : "l"(p));
    return a;
}
__device__ __forceinline__ void cp16(uint32_t d, const void* s) {
    asm volatile("cp.async.cg.shared.global [%0], [%1], 16;" :: "r"(d), "l"(s) : "memory");
}
#define CPC() asm volatile("cp.async.commit_group;" ::: "memory")
#define CPW(n) asm volatile("cp.async.wait_group %0;" :: "n"(n) : "memory")

__device__ __forceinline__ float tr19(float v) {
    return __uint_as_float(__float_as_uint(v) & 0xFFFFE000u);
}
__device__ __forceinline__ void mma8(float* c, const uint32_t* a, const uint32_t* b) {
    asm volatile(
        "mma.sync.aligned.m16n8k8.row.col.f32.tf32.tf32.f32 "
        "{%0,%1,%2,%3},{%4,%5,%6,%7},{%8,%9},{%0,%1,%2,%3};"
        : "+f"(c[0]), "+f"(c[1]), "+f"(c[2]), "+f"(c[3])
        : "r"(a[0]), "r"(a[1]), "r"(a[2]), "r"(a[3]), "r"(b[0]), "r"(b[1]));
}

// ---------------- prep ----------------
__global__ __launch_bounds__(256) void prep_q(
    const float* __restrict__ x_mu, const float* __restrict__ y_eta,
    const float* __restrict__ y_mean, const float* __restrict__ y_var,
    float* __restrict__ out)
{
    int q = blockIdx.x * 8 + (threadIdx.x >> 5), lane = threadIdx.x & 31;
    float a = x_mu[q * 32 + lane];
    float s = y_mean[q * 32 + lane] + y_var[q * 32 + lane];
    float e = 0.01f * y_eta[(NQ - 1 - q) * 32 + lane];
    g_qm[q * 64 + lane] = a;      g_qm[q * 64 + 32 + lane] = s;
    g_qv[q * 96 + lane] = a;      g_qv[q * 96 + 32 + lane] = e;
    g_qv[q * 96 + 64 + lane] = s;
    out[q * 32 + lane] = s;
    float nm = a * a + s * s, nv = nm + e * e;
#pragma unroll
    for (int o = 16; o > 0; o >>= 1) {
        nm += __shfl_xor_sync(~0u, nm, o);
        nv += __shfl_xor_sync(~0u, nv, o);
    }
    if (lane == 0) { g_eqm[q] = __expf(-nm * 0.0078125f); g_eqv[q] = __expf(-nv * 0.0078125f); }
}

template <int D, int V>
__global__ __launch_bounds__(256) void prep_xn(const float* __restrict__ X)
{
    int n = blockIdx.x * 8 + (threadIdx.x >> 5), lane = threadIdx.x & 31;
    float acc = 0.0f;
#pragma unroll
    for (int d = 0; d < D; d += 32) {
        float v = X[(size_t)n * D + d + lane];
        acc = fmaf(v, v, acc);
    }
#pragma unroll
    for (int o = 16; o > 0; o >>= 1) acc += __shfl_xor_sync(~0u, acc, o);
    if (lane == 0) (V ? g_exnv : g_exnm)[n] = __expf(-acc * 0.0078125f);
}

__global__ __launch_bounds__(256) void zeroL() {
    int o = blockIdx.x * 256 + threadIdx.x;
    g_L[0][o] = 0.0f; g_L[1][o] = 0.0f;
}
__global__ __launch_bounds__(256) void scaleL() {
    int o = blockIdx.x * 256 + threadIdx.x;
    int n = o >> 5;
    g_L[0][o] *= g_exnm[n]; g_L[1][o] *= g_exnv[n];
}

// ---------------- Stage A: Lambda = kXX_inv @ Z  (tf32 3-term split) ----------------
// grid (64 row-blocks x 128 rows, 8 k-splits x 1024), block 256 (8 warps).
template <int V>
__global__ __launch_bounds__(256) void stageA(
    const float* __restrict__ A, const float* __restrict__ Z)
{
    __shared__ float sA[2][128 * 36];
    __shared__ float sZ[2][32 * 36];
    int tid = threadIdx.x, wid = tid >> 5, lane = tid & 31;
    int g = lane >> 2, kq = lane & 3;
    size_t r0 = (size_t)blockIdx.x * 128;
    int kb = blockIdx.y * 1024;
    uint32_t sAa = sm_u32(sA), sZa = sm_u32(sZ);

    auto load = [&](int c) {
        int b = c & 1, kc = kb + c * 32;
#pragma unroll
        for (int t = 0; t < 4; t++) {
            int f = tid + 256 * t, r = f >> 3, k4 = f & 7;
            cp16(sAa + b * (128 * 36 * 4) + r * 144 + k4 * 16,
                 A + (r0 + r) * NQ + kc + k4 * 4);
        }
        { int r = tid >> 3, k4 = tid & 7;
          cp16(sZa + b * (32 * 36 * 4) + r * 144 + k4 * 16,
               Z + (size_t)(kc + r) * 32 + k4 * 4); }
        CPC();
    };
    load(0);

    float acc[4][4];
#pragma unroll
    for (int i = 0; i < 4; i++)
#pragma unroll
        for (int j = 0; j < 4; j++) acc[i][j] = 0.0f;

    for (int c = 0; c < 32; c++) {
        int b = c & 1;
        if (c + 1 < 32) { load(c + 1); CPW(1); } else CPW(0);
        __syncthreads();
        const float* pA = sA[b];
        const float* pZ = sZ[b];
#pragma unroll
        for (int ks = 0; ks < 4; ks++) {
            float av[4];
            av[0] = pA[(wid * 16 + g) * 36 + ks * 8 + kq];
            av[1] = pA[(wid * 16 + g + 8) * 36 + ks * 8 + kq];
            av[2] = pA[(wid * 16 + g) * 36 + ks * 8 + kq + 4];
            av[3] = pA[(wid * 16 + g + 8) * 36 + ks * 8 + kq + 4];
            uint32_t ah[4], al[4];
#pragma unroll
            for (int i = 0; i < 4; i++) {
                float h = tr19(av[i]);
                ah[i] = __float_as_uint(h);
                al[i] = __float_as_uint(av[i] - h);
            }
#pragma unroll
            for (int nt = 0; nt < 4; nt++) {
                float b0 = pZ[(ks * 8 + kq) * 36 + nt * 8 + g];
                float b1 = pZ[(ks * 8 + kq + 4) * 36 + nt * 8 + g];
                float h0 = tr19(b0), h1 = tr19(b1);
                uint32_t bh[2] = {__float_as_uint(h0), __float_as_uint(h1)};
                uint32_t bl[2] = {__float_as_uint(b0 - h0), __float_as_uint(b1 - h1)};
                mma8(acc[nt], ah, bh);
                mma8(acc[nt], ah, bl);
                mma8(acc[nt], al, bh);
            }
        }
        __syncthreads();
    }
    float* L = g_L[V];
    size_t ra = r0 + wid * 16 + g;
#pragma unroll
    for (int nt = 0; nt < 4; nt++) {
        int col = nt * 8 + 2 * kq;
        atomicAdd(&L[ra * 32 + col],           acc[nt][0]);
        atomicAdd(&L[ra * 32 + col + 1],       acc[nt][1]);
        atomicAdd(&L[(ra + 8) * 32 + col],     acc[nt][2]);
        atomicAdd(&L[(ra + 8) * 32 + col + 1], acc[nt][3]);
    }
}

// ---------------- Stage B: fused RBF + z  (mma1 single tf32, mma2 3-term) ----------------
// grid (64 q-tiles x 128, 4 n-splits x 2048), block 256, 32 chunks of 64 n.
template <int D, int V>
__global__ __launch_bounds__(256) void stageB(
    const float* __restrict__ Xg, float* __restrict__ out)
{
    const float* Qg = V ? g_qv : g_qm;
    const float* EQ = V ? g_eqv : g_eqm;
    const float* Lg = g_L[V];
    extern __shared__ float smB[];
    const int QP = D + 4;
    float* sQ = smB;                  // 128*QP
    float* sX = sQ + 128 * QP;        // 2 * 64*QP
    float* sK = sX + 2 * 64 * QP;     // 128*68
    float* sL = sK + 128 * 68;        // 2 * 64*36
    uint32_t sQa = sm_u32(sQ), sXa = sm_u32(sX), sLa = sm_u32(sL);
    int tid = threadIdx.x, wid = tid >> 5, lane = tid & 31;
    int g = lane >> 2, kq = lane & 3;
    int q0 = blockIdx.x * 128, nb = blockIdx.y * 2048;
    const int NC = 32;

    for (int idx = tid; idx < 128 * (D / 4); idx += 256) {
        int r = idx / (D / 4), c2 = idx % (D / 4);
        cp16(sQa + (r * QP + c2 * 4) * 4, Qg + (size_t)(q0 + r) * D + c2 * 4);
    }
    auto loadC = [&](int c) {
        int b = c & 1, n0 = nb + c * 64;
        for (int idx = tid; idx < 64 * (D / 4); idx += 256) {
            int r = idx / (D / 4), c2 = idx % (D / 4);
            cp16(sXa + (b * 64 * QP + r * QP + c2 * 4) * 4,
                 Xg + (size_t)(n0 + r) * D + c2 * 4);
        }
#pragma unroll
        for (int t = 0; t < 2; t++) {
            int f = tid + 256 * t, r = f >> 3, c2 = f & 7;
            cp16(sLa + (b * 64 * 36 + r * 36 + c2 * 4) * 4,
                 Lg + (size_t)(n0 + r) * 32 + c2 * 4);
        }
        CPC();
    };
    loadC(0);

    int wm = wid >> 1, wn = wid & 1;
    float z[4][4];
#pragma unroll
    for (int i = 0; i < 4; i++)
#pragma unroll
        for (int j = 0; j < 4; j++) z[i][j] = 0.0f;

    for (int c = 0; c < NC; c++) {
        int b = c & 1;
        if (c + 1 < NC) { loadC(c + 1); CPW(1); } else CPW(0);
        __syncthreads();

        // mma1: S[q][n], warp tile rows wm*32 (2x m16), cols wn*32 (4x n8)
        float s[2][4][4];
#pragma unroll
        for (int mt = 0; mt < 2; mt++)
#pragma unroll
            for (int nt = 0; nt < 4; nt++)
#pragma unroll
                for (int i = 0; i < 4; i++) s[mt][nt][i] = 0.0f;
        const float* pX = sX + b * 64 * QP;
#pragma unroll
        for (int ks = 0; ks < D / 8; ks++) {
            uint32_t a[2][4];
#pragma unroll
            for (int mt = 0; mt < 2; mt++) {
                int r = wm * 32 + mt * 16 + g;
                a[mt][0] = __float_as_uint(sQ[r * QP + ks * 8 + kq]);
                a[mt][1] = __float_as_uint(sQ[(r + 8) * QP + ks * 8 + kq]);
                a[mt][2] = __float_as_uint(sQ[r * QP + ks * 8 + kq + 4]);
                a[mt][3] = __float_as_uint(sQ[(r + 8) * QP + ks * 8 + kq + 4]);
            }
#pragma unroll
            for (int nt = 0; nt < 4; nt++) {
                int n = wn * 32 + nt * 8 + g;
                uint32_t bb[2];
                bb[0] = __float_as_uint(pX[n * QP + ks * 8 + kq]);
                bb[1] = __float_as_uint(pX[n * QP + ks * 8 + kq + 4]);
                mma8(s[0][nt], a[0], bb);
                mma8(s[1][nt], a[1], bb);
            }
        }
        // K = exp(S/64) -> sK
#pragma unroll
        for (int mt = 0; mt < 2; mt++)
#pragma unroll
            for (int nt = 0; nt < 4; nt++) {
                int r = wm * 32 + mt * 16 + g, cc = wn * 32 + nt * 8 + 2 * kq;
                float2 v0, v1;
                v0.x = __expf(s[mt][nt][0] * 0.015625f);
                v0.y = __expf(s[mt][nt][1] * 0.015625f);
                v1.x = __expf(s[mt][nt][2] * 0.015625f);
                v1.y = __expf(s[mt][nt][3] * 0.015625f);
                *reinterpret_cast<float2*>(&sK[r * 68 + cc]) = v0;
                *reinterpret_cast<float2*>(&sK[(r + 8) * 68 + cc]) = v1;
            }
        __syncthreads();

        // mma2: z[q][j] += K * Lam', k = 64 n; warp rows wid*16, all 32 cols
        const float* pL = sL + b * 64 * 36;
#pragma unroll
        for (int ks = 0; ks < 8; ks++) {
            float av[4];
            int r = wid * 16 + g;
            av[0] = sK[r * 68 + ks * 8 + kq];
            av[1] = sK[(r + 8) * 68 + ks * 8 + kq];
            av[2] = sK[r * 68 + ks * 8 + kq + 4];
            av[3] = sK[(r + 8) * 68 + ks * 8 + kq + 4];
            uint32_t ah[4], al[4];
#pragma unroll
            for (int i = 0; i < 4; i++) {
                float h = tr19(av[i]);
                ah[i] = __float_as_uint(h);
                al[i] = __float_as_uint(av[i] - h);
            }
#pragma unroll
            for (int nt = 0; nt < 4; nt++) {
                float b0 = pL[(ks * 8 + kq) * 36 + nt * 8 + g];
                float b1 = pL[(ks * 8 + kq + 4) * 36 + nt * 8 + g];
                float h0 = tr19(b0), h1 = tr19(b1);
                uint32_t bh[2] = {__float_as_uint(h0), __float_as_uint(h1)};
                uint32_t bl[2] = {__float_as_uint(b0 - h0), __float_as_uint(b1 - h1)};
                mma8(z[nt], ah, bh);
                mma8(z[nt], ah, bl);
                mma8(z[nt], al, bh);
            }
        }
        __syncthreads();
    }
    int qa = q0 + wid * 16 + g;
    float e0 = EQ[qa], e1 = EQ[qa + 8];
#pragma unroll
    for (int nt = 0; nt < 4; nt++) {
        int col = nt * 8 + 2 * kq;
        atomicAdd(&out[qa * 32 + col],           e0 * z[nt][0]);
        atomicAdd(&out[qa * 32 + col + 1],       e0 * z[nt][1]);
        atomicAdd(&out[(qa + 8) * 32 + col],     e1 * z[nt][2]);
        atomicAdd(&out[(qa + 8) * 32 + col + 1], e1 * z[nt][3]);
    }
}

// ---------------- launch ----------------
extern "C" void kernel_launch(void* const* d_in, const int* in_sizes, int n_in,
                              void* d_out, int out_size)
{
    const float* x_mu   = (const float*)d_in[0];
    const float* y_eta  = (const float*)d_in[1];
    const float* y_mean = (const float*)d_in[2];
    const float* y_var  = (const float*)d_in[3];
    const float* X_mean = (const float*)d_in[4];
    const float* X_var  = (const float*)d_in[5];
    const float* Z_mean = (const float*)d_in[6];
    const float* Z_var  = (const float*)d_in[7];
    const float* kXXm   = (const float*)d_in[8];
    const float* kXXv   = (const float*)d_in[9];
    float* out = (float*)d_out;

    const int SMB0 = (128 * 68 + 2 * 64 * 68 + 128 * 68 + 2 * 64 * 36) * 4;   // 122880
    const int SMB1 = (128 * 100 + 2 * 64 * 100 + 128 * 68 + 2 * 64 * 36) * 4; // 155648
    cudaFuncSetAttribute(stageB<64, 0>, cudaFuncAttributeMaxDynamicSharedMemorySize, SMB0);
    cudaFuncSetAttribute(stageB<96, 1>, cudaFuncAttributeMaxDynamicSharedMemorySize, SMB1);

    prep_q<<<1024, 256>>>(x_mu, y_eta, y_mean, y_var, out);
    prep_xn<64, 0><<<1024, 256>>>(X_mean);
    prep_xn<96, 1><<<1024, 256>>>(X_var);
    zeroL<<<1024, 256>>>();

    stageA<0><<<dim3(64, 8), 256>>>(kXXm, Z_mean);
    stageA<1><<<dim3(64, 8), 256>>>(kXXv, Z_var);
    scaleL<<<1024, 256>>>();

    stageB<64, 0><<<dim3(64, 4), 256, SMB0>>>(X_mean, out);
    stageB<96, 1><<<dim3(64, 4), 256, SMB1>>>(X_var, out);
}

// round 10
// speedup vs baseline: 3.7104x; 1.3440x over previous
#include <cuda_runtime.h>
#include <cuda_fp16.h>
#include <cstdint>

#define NQ 8192

__device__ __half g_qmh[NQ * 64];
__device__ __half g_qvh[NQ * 96];
__device__ __half g_Xmh[NQ * 64];
__device__ __half g_Xvh[NQ * 96];
__device__ float g_eqm[NQ], g_eqv[NQ], g_exnm[NQ], g_exnv[NQ];
__device__ float g_L[2][NQ * 32];
__device__ __half g_ZTh[2][32 * NQ], g_ZTl[2][32 * NQ];
__device__ __half g_LTh[2][32 * NQ], g_LTl[2][32 * NQ];

__device__ __forceinline__ uint32_t sm_u32(const void* p) {
    uint32_t a;
    asm("{ .reg .u64 t; cvta.to.shared.u64 t, %1; cvt.u32.u64 %0, t; }" : "=r"(a) : "l"(p));
    return a;
}
__device__ __forceinline__ void cp16(uint32_t d, const void* s) {
    asm volatile("cp.async.cg.shared.global [%0], [%1], 16;" :: "r"(d), "l"(s) : "memory");
}
#define CPC() asm volatile("cp.async.commit_group;" ::: "memory")
#define CPW(n) asm volatile("cp.async.wait_group %0;" :: "n"(n) : "memory")

__device__ __forceinline__ void mma16(float* c, const uint32_t* a, const uint32_t* b) {
    asm volatile(
        "mma.sync.aligned.m16n8k16.row.col.f32.f16.f16.f32 "
        "{%0,%1,%2,%3},{%4,%5,%6,%7},{%8,%9},{%0,%1,%2,%3};"
        : "+f"(c[0]), "+f"(c[1]), "+f"(c[2]), "+f"(c[3])
        : "r"(a[0]), "r"(a[1]), "r"(a[2]), "r"(a[3]), "r"(b[0]), "r"(b[1]));
}
__device__ __forceinline__ __half2 splitHi(float x, float y) {
    return __halves2half2(__float2half(x), __float2half(y));
}
__device__ __forceinline__ __half2 splitLo(float x, float y) {
    float hx = __half2float(__float2half(x)), hy = __half2float(__float2half(y));
    return __halves2half2(__float2half((x - hx) * 1024.0f),
                          __float2half((y - hy) * 1024.0f));
}

// ---------------- prep ----------------
__global__ __launch_bounds__(256) void prep_q(
    const float* __restrict__ x_mu, const float* __restrict__ y_eta,
    const float* __restrict__ y_mean, const float* __restrict__ y_var,
    float* __restrict__ out)
{
    int q = blockIdx.x * 8 + (threadIdx.x >> 5), lane = threadIdx.x & 31;
    float a = x_mu[q * 32 + lane];
    float s = y_mean[q * 32 + lane] + y_var[q * 32 + lane];
    float e = 0.01f * y_eta[(NQ - 1 - q) * 32 + lane];
    g_qmh[q * 64 + lane] = __float2half(a);
    g_qmh[q * 64 + 32 + lane] = __float2half(s);
    g_qvh[q * 96 + lane] = __float2half(a);
    g_qvh[q * 96 + 32 + lane] = __float2half(e);
    g_qvh[q * 96 + 64 + lane] = __float2half(s);
    out[q * 32 + lane] = s;
    float nm = a * a + s * s, nv = nm + e * e;
#pragma unroll
    for (int o = 16; o > 0; o >>= 1) {
        nm += __shfl_xor_sync(~0u, nm, o);
        nv += __shfl_xor_sync(~0u, nv, o);
    }
    if (lane == 0) { g_eqm[q] = __expf(-nm * 0.0078125f); g_eqv[q] = __expf(-nv * 0.0078125f); }
}

template <int D, int V>
__global__ __launch_bounds__(256) void prep_xn(const float* __restrict__ X)
{
    int n = blockIdx.x * 8 + (threadIdx.x >> 5), lane = threadIdx.x & 31;
    __half* Xh = V ? g_Xvh : g_Xmh;
    float acc = 0.0f;
#pragma unroll
    for (int d = 0; d < D; d += 32) {
        float v = X[(size_t)n * D + d + lane];
        Xh[(size_t)n * D + d + lane] = __float2half(v);
        acc = fmaf(v, v, acc);
    }
#pragma unroll
    for (int o = 16; o > 0; o >>= 1) acc += __shfl_xor_sync(~0u, acc, o);
    if (lane == 0) (V ? g_exnv : g_exnm)[n] = __expf(-acc * 0.0078125f);
}

__global__ __launch_bounds__(256) void prep_zt(
    const float* __restrict__ Zm, const float* __restrict__ Zv)
{
    int o = blockIdx.x * 256 + threadIdx.x;      // 1024 blocks -> 262144
    int j = o >> 13, n = o & (NQ - 1);
    float zm = Zm[n * 32 + j], zv = Zv[n * 32 + j];
    g_ZTh[0][o] = __low2half(splitHi(zm, zm)); g_ZTl[0][o] = __low2half(splitLo(zm, zm));
    g_ZTh[1][o] = __low2half(splitHi(zv, zv)); g_ZTl[1][o] = __low2half(splitLo(zv, zv));
    g_L[0][o] = 0.0f; g_L[1][o] = 0.0f;
}

__global__ __launch_bounds__(256) void scaleL()
{
    int o = blockIdx.x * 256 + threadIdx.x;
    int j = o >> 13, n = o & (NQ - 1);
    float a = g_L[0][n * 32 + j] * g_exnm[n];
    float b = g_L[1][n * 32 + j] * g_exnv[n];
    g_LTh[0][o] = __low2half(splitHi(a, a)); g_LTl[0][o] = __low2half(splitLo(a, a));
    g_LTh[1][o] = __low2half(splitHi(b, b)); g_LTl[1][o] = __low2half(splitLo(b, b));
}

// ---------------- Stage A: Lambda = kXX_inv @ Z  (fp16 3-term, scaled lo) ----------------
// grid (64 row-blocks x 128, 8 k-splits x 1024), block 256 (8 warps), 32 chunks of k32.
template <int V>
__global__ __launch_bounds__(256, 2) void stageA(const float* __restrict__ A)
{
    extern __shared__ char smA[];
    float*  sAf = (float*)smA;                           // [2][128*36]
    __half* sAh = (__half*)(smA + 2 * 128 * 36 * 4);     // [2][128*40]
    __half* sAl = sAh + 2 * 128 * 40;
    __half* sZh = sAl + 2 * 128 * 40;                    // [2][32*40]
    __half* sZl = sZh + 2 * 32 * 40;
    int tid = threadIdx.x, wid = tid >> 5, lane = tid & 31;
    int g = lane >> 2, kq = lane & 3;
    size_t r0 = (size_t)blockIdx.x * 128;
    int kb = blockIdx.y * 1024;
    uint32_t aAf = sm_u32(sAf), aZh = sm_u32(sZh), aZl = sm_u32(sZl);

    auto load = [&](int c) {
        int b = c & 1, kc = kb + c * 32;
#pragma unroll
        for (int t = 0; t < 4; t++) {
            int f = tid + 256 * t, r = f >> 3, kg = f & 7;
            cp16(aAf + (b * 128 * 36 + r * 36 + kg * 4) * 4,
                 A + (r0 + r) * NQ + kc + kg * 4);
        }
        {
            int h = tid >> 7, rem = tid & 127, j = rem >> 2, kg = rem & 3;
            const __half* src = h ? g_ZTl[V] : g_ZTh[V];
            cp16((h ? aZl : aZh) + (b * 32 * 40 + j * 40 + kg * 8) * 2,
                 src + (size_t)j * NQ + kc + kg * 8);
        }
        CPC();
    };
    load(0);

    float accH[4][4], accL[4][4];
#pragma unroll
    for (int i = 0; i < 4; i++)
#pragma unroll
        for (int j = 0; j < 4; j++) { accH[i][j] = 0.0f; accL[i][j] = 0.0f; }

    for (int c = 0; c < 32; c++) {
        int b = c & 1;
        if (c + 1 < 32) { load(c + 1); CPW(1); } else CPW(0);
        __syncthreads();
        // convert fp32 A chunk -> (hi, lo*1024) halves
#pragma unroll
        for (int t = 0; t < 8; t++) {
            int idx = tid + 256 * t;                 // 2048 float2 pairs
            int r = idx >> 4, kp = idx & 15;
            float2 v = *(float2*)&sAf[b * 128 * 36 + r * 36 + kp * 2];
            *(__half2*)&sAh[b * 128 * 40 + r * 40 + kp * 2] = splitHi(v.x, v.y);
            *(__half2*)&sAl[b * 128 * 40 + r * 40 + kp * 2] = splitLo(v.x, v.y);
        }
        __syncthreads();
        const __half* pAh = sAh + b * 128 * 40;
        const __half* pAl = sAl + b * 128 * 40;
        const __half* pZh = sZh + b * 32 * 40;
        const __half* pZl = sZl + b * 32 * 40;
        int rA = wid * 16 + g;
#pragma unroll
        for (int ks = 0; ks < 2; ks++) {
            int ko = ks * 16 + 2 * kq;
            uint32_t ah[4], al[4];
            ah[0] = *(const uint32_t*)&pAh[rA * 40 + ko];
            ah[1] = *(const uint32_t*)&pAh[(rA + 8) * 40 + ko];
            ah[2] = *(const uint32_t*)&pAh[rA * 40 + ko + 8];
            ah[3] = *(const uint32_t*)&pAh[(rA + 8) * 40 + ko + 8];
            al[0] = *(const uint32_t*)&pAl[rA * 40 + ko];
            al[1] = *(const uint32_t*)&pAl[(rA + 8) * 40 + ko];
            al[2] = *(const uint32_t*)&pAl[rA * 40 + ko + 8];
            al[3] = *(const uint32_t*)&pAl[(rA + 8) * 40 + ko + 8];
#pragma unroll
            for (int nt = 0; nt < 4; nt++) {
                int rB = nt * 8 + g;
                uint32_t bh[2], bl[2];
                bh[0] = *(const uint32_t*)&pZh[rB * 40 + ko];
                bh[1] = *(const uint32_t*)&pZh[rB * 40 + ko + 8];
                bl[0] = *(const uint32_t*)&pZl[rB * 40 + ko];
                bl[1] = *(const uint32_t*)&pZl[rB * 40 + ko + 8];
                mma16(accH[nt], ah, bh);
                mma16(accL[nt], ah, bl);
                mma16(accL[nt], al, bh);
            }
        }
        __syncthreads();   // REQUIRED: next iter's cp.async reuses buffer b
    }
    float* L = g_L[V];
    size_t ra = r0 + wid * 16 + g;
#pragma unroll
    for (int nt = 0; nt < 4; nt++) {
        int col = nt * 8 + 2 * kq;
        atomicAdd(&L[ra * 32 + col],           accH[nt][0] + accL[nt][0] * 9.765625e-4f);
        atomicAdd(&L[ra * 32 + col + 1],       accH[nt][1] + accL[nt][1] * 9.765625e-4f);
        atomicAdd(&L[(ra + 8) * 32 + col],     accH[nt][2] + accL[nt][2] * 9.765625e-4f);
        atomicAdd(&L[(ra + 8) * 32 + col + 1], accH[nt][3] + accL[nt][3] * 9.765625e-4f);
    }
}

// ---------------- Stage B: fused RBF + z  (fp16; mma2 3-term scaled lo) ----------------
// grid (64 q-tiles x 128, 4 n-splits x 2048), block 256, 32 chunks of 64 n.
template <int D, int V>
__global__ __launch_bounds__(256) void stageB(float* __restrict__ out)
{
    const __half* Qg = V ? g_qvh : g_qmh;
    const __half* Xg = V ? g_Xvh : g_Xmh;
    const float*  EQ = V ? g_eqv : g_eqm;
    extern __shared__ __half smB[];
    const int SP = D + 8;
    __half* sQ  = smB;                    // [128][SP]
    __half* sX  = sQ + 128 * SP;          // [2][64][SP]
    __half* sKh = sX + 2 * 64 * SP;       // [128][72]
    __half* sKl = sKh + 128 * 72;
    __half* sLh = sKl + 128 * 72;         // [2][32][72]
    __half* sLl = sLh + 2 * 32 * 72;
    uint32_t aQ = sm_u32(sQ), aX = sm_u32(sX), aLh = sm_u32(sLh), aLl = sm_u32(sLl);
    int tid = threadIdx.x, wid = tid >> 5, lane = tid & 31;
    int g = lane >> 2, kq = lane & 3;
    int wm = wid >> 1, wn = wid & 1;
    int q0 = blockIdx.x * 128, nb = blockIdx.y * 2048;
    const int NC = 32;

    for (int idx = tid; idx < 128 * (D / 8); idx += 256) {
        int r = idx / (D / 8), kg = idx % (D / 8);
        cp16(aQ + (r * SP + kg * 8) * 2, Qg + (size_t)(q0 + r) * D + kg * 8);
    }
    auto loadC = [&](int c) {
        int b = c & 1, n0 = nb + c * 64;
        for (int idx = tid; idx < 64 * (D / 8); idx += 256) {
            int r = idx / (D / 8), kg = idx % (D / 8);
            cp16(aX + (b * 64 * SP + r * SP + kg * 8) * 2,
                 Xg + (size_t)(n0 + r) * D + kg * 8);
        }
#pragma unroll
        for (int t = 0; t < 2; t++) {
            int f = tid + 256 * t;
            int h = f >> 8, rem = f & 255, j = rem >> 3, kg = rem & 7;
            const __half* src = h ? g_LTl[V] : g_LTh[V];
            cp16((h ? aLl : aLh) + (b * 32 * 72 + j * 72 + kg * 8) * 2,
                 src + (size_t)j * NQ + n0 + kg * 8);
        }
        CPC();
    };
    loadC(0);

    float zH[4][4], zL[4][4];
#pragma unroll
    for (int i = 0; i < 4; i++)
#pragma unroll
        for (int j = 0; j < 4; j++) { zH[i][j] = 0.0f; zL[i][j] = 0.0f; }

    for (int c = 0; c < NC; c++) {
        int b = c & 1;
        if (c + 1 < NC) { loadC(c + 1); CPW(1); } else CPW(0);
        __syncthreads();

        // mma1: S[q][n] = Q . X^T
        float s[2][4][4];
#pragma unroll
        for (int mt = 0; mt < 2; mt++)
#pragma unroll
            for (int nt = 0; nt < 4; nt++)
#pragma unroll
                for (int i = 0; i < 4; i++) s[mt][nt][i] = 0.0f;
        const __half* pX = sX + b * 64 * SP;
#pragma unroll
        for (int ks = 0; ks < D / 16; ks++) {
            int ko = ks * 16 + 2 * kq;
            uint32_t a2[2][4];
#pragma unroll
            for (int mt = 0; mt < 2; mt++) {
                int r = wm * 32 + mt * 16 + g;
                a2[mt][0] = *(const uint32_t*)&sQ[r * SP + ko];
                a2[mt][1] = *(const uint32_t*)&sQ[(r + 8) * SP + ko];
                a2[mt][2] = *(const uint32_t*)&sQ[r * SP + ko + 8];
                a2[mt][3] = *(const uint32_t*)&sQ[(r + 8) * SP + ko + 8];
            }
#pragma unroll
            for (int nt = 0; nt < 4; nt++) {
                int n = wn * 32 + nt * 8 + g;
                uint32_t bb[2];
                bb[0] = *(const uint32_t*)&pX[n * SP + ko];
                bb[1] = *(const uint32_t*)&pX[n * SP + ko + 8];
                mma16(s[0][nt], a2[0], bb);
                mma16(s[1][nt], a2[1], bb);
            }
        }
        // K = exp(S/64) -> sK (hi + scaled lo halves)
#pragma unroll
        for (int mt = 0; mt < 2; mt++)
#pragma unroll
            for (int nt = 0; nt < 4; nt++) {
                int r = wm * 32 + mt * 16 + g, cc = wn * 32 + nt * 8 + 2 * kq;
                float e0 = __expf(s[mt][nt][0] * 0.015625f);
                float e1 = __expf(s[mt][nt][1] * 0.015625f);
                float e2 = __expf(s[mt][nt][2] * 0.015625f);
                float e3 = __expf(s[mt][nt][3] * 0.015625f);
                *(__half2*)&sKh[r * 72 + cc]       = splitHi(e0, e1);
                *(__half2*)&sKl[r * 72 + cc]       = splitLo(e0, e1);
                *(__half2*)&sKh[(r + 8) * 72 + cc] = splitHi(e2, e3);
                *(__half2*)&sKl[(r + 8) * 72 + cc] = splitLo(e2, e3);
            }
        __syncthreads();

        // mma2: z[q][j] += K . Lam'^T, k = 64 n
        const __half* pLh = sLh + b * 32 * 72;
        const __half* pLl = sLl + b * 32 * 72;
        int rA = wid * 16 + g;
#pragma unroll
        for (int ks = 0; ks < 4; ks++) {
            int ko = ks * 16 + 2 * kq;
            uint32_t ah[4], al[4];
            ah[0] = *(const uint32_t*)&sKh[rA * 72 + ko];
            ah[1] = *(const uint32_t*)&sKh[(rA + 8) * 72 + ko];
            ah[2] = *(const uint32_t*)&sKh[rA * 72 + ko + 8];
            ah[3] = *(const uint32_t*)&sKh[(rA + 8) * 72 + ko + 8];
            al[0] = *(const uint32_t*)&sKl[rA * 72 + ko];
            al[1] = *(const uint32_t*)&sKl[(rA + 8) * 72 + ko];
            al[2] = *(const uint32_t*)&sKl[rA * 72 + ko + 8];
            al[3] = *(const uint32_t*)&sKl[(rA + 8) * 72 + ko + 8];
#pragma unroll
            for (int nt = 0; nt < 4; nt++) {
                int rB = nt * 8 + g;
                uint32_t bh[2], bl[2];
                bh[0] = *(const uint32_t*)&pLh[rB * 72 + ko];
                bh[1] = *(const uint32_t*)&pLh[rB * 72 + ko + 8];
                bl[0] = *(const uint32_t*)&pLl[rB * 72 + ko];
                bl[1] = *(const uint32_t*)&pLl[rB * 72 + ko + 8];
                mma16(zH[nt], ah, bh);
                mma16(zL[nt], ah, bl);
                mma16(zL[nt], al, bh);
            }
        }
        __syncthreads();
    }
    int qa = q0 + wid * 16 + g;
    float e0 = EQ[qa], e1 = EQ[qa + 8];
#pragma unroll
    for (int nt = 0; nt < 4; nt++) {
        int col = nt * 8 + 2 * kq;
        atomicAdd(&out[qa * 32 + col],           e0 * (zH[nt][0] + zL[nt][0] * 9.765625e-4f));
        atomicAdd(&out[qa * 32 + col + 1],       e0 * (zH[nt][1] + zL[nt][1] * 9.765625e-4f));
        atomicAdd(&out[(qa + 8) * 32 + col],     e1 * (zH[nt][2] + zL[nt][2] * 9.765625e-4f));
        atomicAdd(&out[(qa + 8) * 32 + col + 1], e1 * (zH[nt][3] + zL[nt][3] * 9.765625e-4f));
    }
}

// ---------------- launch ----------------
extern "C" void kernel_launch(void* const* d_in, const int* in_sizes, int n_in,
                              void* d_out, int out_size)
{
    const float* x_mu   = (const float*)d_in[0];
    const float* y_eta  = (const float*)d_in[1];
    const float* y_mean = (const float*)d_in[2];
    const float* y_var  = (const float*)d_in[3];
    const float* X_mean = (const float*)d_in[4];
    const float* X_var  = (const float*)d_in[5];
    const float* Z_mean = (const float*)d_in[6];
    const float* Z_var  = (const float*)d_in[7];
    const float* kXXm   = (const float*)d_in[8];
    const float* kXXv   = (const float*)d_in[9];
    float* out = (float*)d_out;

    const int SMA  = 2 * 128 * 36 * 4 + 4 * 128 * 40 * 2 + 4 * 32 * 40 * 2;   // 88064
    const int SMB0 = (128 * 72 + 2 * 64 * 72 + 2 * 128 * 72 + 4 * 32 * 72) * 2;  // 92160
    const int SMB1 = (128 * 104 + 2 * 64 * 104 + 2 * 128 * 72 + 4 * 32 * 72) * 2; // 108544
    cudaFuncSetAttribute(stageA<0>, cudaFuncAttributeMaxDynamicSharedMemorySize, SMA);
    cudaFuncSetAttribute(stageA<1>, cudaFuncAttributeMaxDynamicSharedMemorySize, SMA);
    cudaFuncSetAttribute(stageB<64, 0>, cudaFuncAttributeMaxDynamicSharedMemorySize, SMB0);
    cudaFuncSetAttribute(stageB<96, 1>, cudaFuncAttributeMaxDynamicSharedMemorySize, SMB1);

    prep_q<<<1024, 256>>>(x_mu, y_eta, y_mean, y_var, out);
    prep_xn<64, 0><<<1024, 256>>>(X_mean);
    prep_xn<96, 1><<<1024, 256>>>(X_var);
    prep_zt<<<1024, 256>>>(Z_mean, Z_var);

    stageA<0><<<dim3(64, 8), 256, SMA>>>(kXXm);
    stageA<1><<<dim3(64, 8), 256, SMA>>>(kXXv);
    scaleL<<<1024, 256>>>();

    stageB<64, 0><<<dim3(64, 4), 256, SMB0>>>(out);
    stageB<96, 1><<<dim3(64, 4), 256, SMB1>>>(out);
}

// round 11
// speedup vs baseline: 4.9279x; 1.3281x over previous
#include <cuda_runtime.h>
#include <cuda_fp16.h>
#include <cstdint>

#define NQ 8192

__device__ __half g_qmh[NQ * 64];
__device__ __half g_qvh[NQ * 96];
__device__ __half g_Xmh[NQ * 64];
__device__ __half g_Xvh[NQ * 96];
__device__ float g_eqm[NQ], g_eqv[NQ], g_exnm[NQ], g_exnv[NQ];
__device__ float g_L[2][NQ * 32];
__device__ __half g_ZTh[2][32 * NQ], g_ZTl[2][32 * NQ];
__device__ __half g_LTh[2][32 * NQ], g_LTl[2][32 * NQ];

__device__ __forceinline__ uint32_t sm_u32(const void* p) {
    uint32_t a;
    asm("{ .reg .u64 t; cvta.to.shared.u64 t, %1; cvt.u32.u64 %0, t; }" : "=r"(a) : "l"(p));
    return a;
}
__device__ __forceinline__ void cp16(uint32_t d, const void* s) {
    asm volatile("cp.async.cg.shared.global [%0], [%1], 16;" :: "r"(d), "l"(s) : "memory");
}
#define CPC() asm volatile("cp.async.commit_group;" ::: "memory")
#define CPW(n) asm volatile("cp.async.wait_group %0;" :: "n"(n) : "memory")

__device__ __forceinline__ void mma16(float* c, const uint32_t* a, const uint32_t* b) {
    asm volatile(
        "mma.sync.aligned.m16n8k16.row.col.f32.f16.f16.f32 "
        "{%0,%1,%2,%3},{%4,%5,%6,%7},{%8,%9},{%0,%1,%2,%3};"
        : "+f"(c[0]), "+f"(c[1]), "+f"(c[2]), "+f"(c[3])
        : "r"(a[0]), "r"(a[1]), "r"(a[2]), "r"(a[3]), "r"(b[0]), "r"(b[1]));
}
__device__ __forceinline__ __half2 splitHi(float x, float y) {
    return __halves2half2(__float2half(x), __float2half(y));
}
__device__ __forceinline__ __half2 splitLo(float x, float y) {
    float hx = __half2float(__float2half(x)), hy = __half2float(__float2half(y));
    return __halves2half2(__float2half((x - hx) * 1024.0f),
                          __float2half((y - hy) * 1024.0f));
}
__device__ __forceinline__ uint32_t packh(float x, float y) {
    __half2 h = __halves2half2(__float2half(x), __float2half(y));
    return *reinterpret_cast<uint32_t*>(&h);
}

// ---------------- prep ----------------
__global__ __launch_bounds__(256) void prep_q(
    const float* __restrict__ x_mu, const float* __restrict__ y_eta,
    const float* __restrict__ y_mean, const float* __restrict__ y_var,
    float* __restrict__ out)
{
    int q = blockIdx.x * 8 + (threadIdx.x >> 5), lane = threadIdx.x & 31;
    float a = x_mu[q * 32 + lane];
    float s = y_mean[q * 32 + lane] + y_var[q * 32 + lane];
    float e = 0.01f * y_eta[(NQ - 1 - q) * 32 + lane];
    g_qmh[q * 64 + lane] = __float2half(a);
    g_qmh[q * 64 + 32 + lane] = __float2half(s);
    g_qvh[q * 96 + lane] = __float2half(a);
    g_qvh[q * 96 + 32 + lane] = __float2half(e);
    g_qvh[q * 96 + 64 + lane] = __float2half(s);
    out[q * 32 + lane] = s;
    float nm = a * a + s * s, nv = nm + e * e;
#pragma unroll
    for (int o = 16; o > 0; o >>= 1) {
        nm += __shfl_xor_sync(~0u, nm, o);
        nv += __shfl_xor_sync(~0u, nv, o);
    }
    if (lane == 0) { g_eqm[q] = __expf(-nm * 0.0078125f); g_eqv[q] = __expf(-nv * 0.0078125f); }
}

template <int D, int V>
__global__ __launch_bounds__(256) void prep_xn(const float* __restrict__ X)
{
    int n = blockIdx.x * 8 + (threadIdx.x >> 5), lane = threadIdx.x & 31;
    __half* Xh = V ? g_Xvh : g_Xmh;
    float acc = 0.0f;
#pragma unroll
    for (int d = 0; d < D; d += 32) {
        float v = X[(size_t)n * D + d + lane];
        Xh[(size_t)n * D + d + lane] = __float2half(v);
        acc = fmaf(v, v, acc);
    }
#pragma unroll
    for (int o = 16; o > 0; o >>= 1) acc += __shfl_xor_sync(~0u, acc, o);
    if (lane == 0) (V ? g_exnv : g_exnm)[n] = __expf(-acc * 0.0078125f);
}

__global__ __launch_bounds__(256) void prep_zt(
    const float* __restrict__ Zm, const float* __restrict__ Zv)
{
    int o = blockIdx.x * 256 + threadIdx.x;
    int j = o >> 13, n = o & (NQ - 1);
    float zm = Zm[n * 32 + j], zv = Zv[n * 32 + j];
    g_ZTh[0][o] = __low2half(splitHi(zm, zm)); g_ZTl[0][o] = __low2half(splitLo(zm, zm));
    g_ZTh[1][o] = __low2half(splitHi(zv, zv)); g_ZTl[1][o] = __low2half(splitLo(zv, zv));
    g_L[0][o] = 0.0f; g_L[1][o] = 0.0f;
}

__global__ __launch_bounds__(256) void scaleL()
{
    int o = blockIdx.x * 256 + threadIdx.x;
    int j = o >> 13, n = o & (NQ - 1);
    float a = g_L[0][n * 32 + j] * g_exnm[n];
    float b = g_L[1][n * 32 + j] * g_exnv[n];
    g_LTh[0][o] = __low2half(splitHi(a, a)); g_LTl[0][o] = __low2half(splitLo(a, a));
    g_LTh[1][o] = __low2half(splitHi(b, b)); g_LTl[1][o] = __low2half(splitLo(b, b));
}

// ---------------- Stage A: Lambda = kXX_inv @ Z  (fp16 2-term: Ah*(Zh+Zl)) ----------------
// grid (64 row-blocks x 128, 4 k-splits x 2048), block 256, occ 2, 64 chunks of k32.
template <int V>
__global__ __launch_bounds__(256, 2) void stageA(const float* __restrict__ A)
{
    extern __shared__ char smA[];
    float*  sAf = (float*)smA;                           // [2][128*36]
    __half* sAh = (__half*)(smA + 36864);                // [2][128*40]
    __half* sZh = (__half*)(smA + 36864 + 20480);        // [2][32*40]
    __half* sZl = sZh + 2 * 32 * 40;
    int tid = threadIdx.x, wid = tid >> 5, lane = tid & 31;
    int g = lane >> 2, kq = lane & 3;
    size_t r0 = (size_t)blockIdx.x * 128;
    int kb = blockIdx.y * 2048;
    uint32_t aAf = sm_u32(sAf), aZh = sm_u32(sZh), aZl = sm_u32(sZl);

    auto load = [&](int c) {
        int b = c & 1, kc = kb + c * 32;
#pragma unroll
        for (int t = 0; t < 4; t++) {
            int f = tid + 256 * t, r = f >> 3, kg = f & 7;
            cp16(aAf + (b * 128 * 36 + r * 36 + kg * 4) * 4,
                 A + (r0 + r) * NQ + kc + kg * 4);
        }
        {
            int h = tid >> 7, rem = tid & 127, j = rem >> 2, kg = rem & 3;
            const __half* src = h ? g_ZTl[V] : g_ZTh[V];
            cp16((h ? aZl : aZh) + (b * 32 * 40 + j * 40 + kg * 8) * 2,
                 src + (size_t)j * NQ + kc + kg * 8);
        }
        CPC();
    };
    load(0);

    float accH[4][4], accL[4][4];
#pragma unroll
    for (int i = 0; i < 4; i++)
#pragma unroll
        for (int j = 0; j < 4; j++) { accH[i][j] = 0.0f; accL[i][j] = 0.0f; }

    for (int c = 0; c < 64; c++) {
        int b = c & 1;
        if (c + 1 < 64) { load(c + 1); CPW(1); } else CPW(0);
        __syncthreads();
#pragma unroll
        for (int t = 0; t < 8; t++) {
            int idx = tid + 256 * t;
            int r = idx >> 4, kp = idx & 15;
            float2 v = *(float2*)&sAf[b * 128 * 36 + r * 36 + kp * 2];
            *(__half2*)&sAh[b * 128 * 40 + r * 40 + kp * 2] = splitHi(v.x, v.y);
        }
        __syncthreads();
        const __half* pAh = sAh + b * 128 * 40;
        const __half* pZh = sZh + b * 32 * 40;
        const __half* pZl = sZl + b * 32 * 40;
        int rA = wid * 16 + g;
#pragma unroll
        for (int ks = 0; ks < 2; ks++) {
            int ko = ks * 16 + 2 * kq;
            uint32_t ah[4];
            ah[0] = *(const uint32_t*)&pAh[rA * 40 + ko];
            ah[1] = *(const uint32_t*)&pAh[(rA + 8) * 40 + ko];
            ah[2] = *(const uint32_t*)&pAh[rA * 40 + ko + 8];
            ah[3] = *(const uint32_t*)&pAh[(rA + 8) * 40 + ko + 8];
#pragma unroll
            for (int nt = 0; nt < 4; nt++) {
                int rB = nt * 8 + g;
                uint32_t bh[2], bl[2];
                bh[0] = *(const uint32_t*)&pZh[rB * 40 + ko];
                bh[1] = *(const uint32_t*)&pZh[rB * 40 + ko + 8];
                bl[0] = *(const uint32_t*)&pZl[rB * 40 + ko];
                bl[1] = *(const uint32_t*)&pZl[rB * 40 + ko + 8];
                mma16(accH[nt], ah, bh);
                mma16(accL[nt], ah, bl);
            }
        }
        __syncthreads();
    }
    float* L = g_L[V];
    size_t ra = r0 + wid * 16 + g;
#pragma unroll
    for (int nt = 0; nt < 4; nt++) {
        int col = nt * 8 + 2 * kq;
        atomicAdd(&L[ra * 32 + col],           accH[nt][0] + accL[nt][0] * 9.765625e-4f);
        atomicAdd(&L[ra * 32 + col + 1],       accH[nt][1] + accL[nt][1] * 9.765625e-4f);
        atomicAdd(&L[(ra + 8) * 32 + col],     accH[nt][2] + accL[nt][2] * 9.765625e-4f);
        atomicAdd(&L[(ra + 8) * 32 + col + 1], accH[nt][3] + accL[nt][3] * 9.765625e-4f);
    }
}

// ---------------- Stage B: fused RBF + z, K kept in registers ----------------
// grid (64 q-tiles x 128, 4 n-splits x 2048), block 256, occ 2, 32 chunks of 64 n.
// Warp (wm = wid>>1, wn = wid&1): mma1 tile 32q x 32n; its accumulators become
// mma2 A-fragments (k = n). Each wn half accumulates z over its 32-n slice;
// both halves atomicAdd at the end.
template <int D, int V>
__global__ __launch_bounds__(256, 2) void stageB(float* __restrict__ out)
{
    const __half* Qg = V ? g_qvh : g_qmh;
    const __half* Xg = V ? g_Xvh : g_Xmh;
    const float*  EQ = V ? g_eqv : g_eqm;
    extern __shared__ __half smB[];
    const int SP = D + 8;
    __half* sQ  = smB;                    // [128][SP]
    __half* sX  = sQ + 128 * SP;          // [2][64][SP]
    __half* sLh = sX + 2 * 64 * SP;       // [2][32 j][72 n]
    __half* sLl = sLh + 2 * 32 * 72;
    uint32_t aQ = sm_u32(sQ), aX = sm_u32(sX), aLh = sm_u32(sLh), aLl = sm_u32(sLl);
    int tid = threadIdx.x, wid = tid >> 5, lane = tid & 31;
    int g = lane >> 2, kq = lane & 3;
    int wm = wid >> 1, wn = wid & 1;
    int q0 = blockIdx.x * 128, nb = blockIdx.y * 2048;
    const int NC = 32;

    for (int idx = tid; idx < 128 * (D / 8); idx += 256) {
        int r = idx / (D / 8), kg = idx % (D / 8);
        cp16(aQ + (r * SP + kg * 8) * 2, Qg + (size_t)(q0 + r) * D + kg * 8);
    }
    auto loadC = [&](int c) {
        int b = c & 1, n0 = nb + c * 64;
        for (int idx = tid; idx < 64 * (D / 8); idx += 256) {
            int r = idx / (D / 8), kg = idx % (D / 8);
            cp16(aX + (b * 64 * SP + r * SP + kg * 8) * 2,
                 Xg + (size_t)(n0 + r) * D + kg * 8);
        }
#pragma unroll
        for (int t = 0; t < 2; t++) {
            int f = tid + 256 * t;
            int h = f >> 8, rem = f & 255, j = rem >> 3, kg = rem & 7;
            const __half* src = h ? g_LTl[V] : g_LTh[V];
            cp16((h ? aLl : aLh) + (b * 32 * 72 + j * 72 + kg * 8) * 2,
                 src + (size_t)j * NQ + n0 + kg * 8);
        }
        CPC();
    };
    loadC(0);

    float zH[2][4][4], zL[2][4][4];
#pragma unroll
    for (int m = 0; m < 2; m++)
#pragma unroll
        for (int i = 0; i < 4; i++)
#pragma unroll
            for (int j = 0; j < 4; j++) { zH[m][i][j] = 0.0f; zL[m][i][j] = 0.0f; }

    for (int c = 0; c < NC; c++) {
        int b = c & 1;
        if (c + 1 < NC) { loadC(c + 1); CPW(1); } else CPW(0);
        __syncthreads();

        // mma1: S = Q . X^T for this warp's 32q x 32n tile
        float s[2][4][4];
#pragma unroll
        for (int mt = 0; mt < 2; mt++)
#pragma unroll
            for (int nt = 0; nt < 4; nt++)
#pragma unroll
                for (int i = 0; i < 4; i++) s[mt][nt][i] = 0.0f;
        const __half* pX = sX + b * 64 * SP;
#pragma unroll
        for (int ks = 0; ks < D / 16; ks++) {
            int ko = ks * 16 + 2 * kq;
            uint32_t a2[2][4];
#pragma unroll
            for (int mt = 0; mt < 2; mt++) {
                int r = wm * 32 + mt * 16 + g;
                a2[mt][0] = *(const uint32_t*)&sQ[r * SP + ko];
                a2[mt][1] = *(const uint32_t*)&sQ[(r + 8) * SP + ko];
                a2[mt][2] = *(const uint32_t*)&sQ[r * SP + ko + 8];
                a2[mt][3] = *(const uint32_t*)&sQ[(r + 8) * SP + ko + 8];
            }
#pragma unroll
            for (int nt = 0; nt < 4; nt++) {
                int n = wn * 32 + nt * 8 + g;
                uint32_t bb[2];
                bb[0] = *(const uint32_t*)&pX[n * SP + ko];
                bb[1] = *(const uint32_t*)&pX[n * SP + ko + 8];
                mma16(s[0][nt], a2[0], bb);
                mma16(s[1][nt], a2[1], bb);
            }
        }
        // K = exp(S/64) packed directly into mma2 A-fragments (k = n dim)
        uint32_t ka[2][2][4];
#pragma unroll
        for (int mt = 0; mt < 2; mt++)
#pragma unroll
            for (int nt = 0; nt < 4; nt++) {
#pragma unroll
                for (int i = 0; i < 4; i++)
                    s[mt][nt][i] = __expf(s[mt][nt][i] * 0.015625f);
            }
#pragma unroll
        for (int mt = 0; mt < 2; mt++)
#pragma unroll
            for (int ks = 0; ks < 2; ks++) {
                ka[mt][ks][0] = packh(s[mt][2 * ks][0],     s[mt][2 * ks][1]);
                ka[mt][ks][1] = packh(s[mt][2 * ks][2],     s[mt][2 * ks][3]);
                ka[mt][ks][2] = packh(s[mt][2 * ks + 1][0], s[mt][2 * ks + 1][1]);
                ka[mt][ks][3] = packh(s[mt][2 * ks + 1][2], s[mt][2 * ks + 1][3]);
            }

        // mma2: z += K . Lam'^T over this warp's 32-n slice
        const __half* pLh = sLh + b * 32 * 72;
        const __half* pLl = sLl + b * 32 * 72;
#pragma unroll
        for (int ks = 0; ks < 2; ks++) {
            int ko = wn * 32 + ks * 16 + 2 * kq;
#pragma unroll
            for (int jt = 0; jt < 4; jt++) {
                int rB = jt * 8 + g;
                uint32_t bh[2], bl[2];
                bh[0] = *(const uint32_t*)&pLh[rB * 72 + ko];
                bh[1] = *(const uint32_t*)&pLh[rB * 72 + ko + 8];
                bl[0] = *(const uint32_t*)&pLl[rB * 72 + ko];
                bl[1] = *(const uint32_t*)&pLl[rB * 72 + ko + 8];
                mma16(zH[0][jt], ka[0][ks], bh);
                mma16(zL[0][jt], ka[0][ks], bl);
                mma16(zH[1][jt], ka[1][ks], bh);
                mma16(zL[1][jt], ka[1][ks], bl);
            }
        }
        __syncthreads();
    }
#pragma unroll
    for (int mt = 0; mt < 2; mt++) {
        int qa = q0 + wm * 32 + mt * 16 + g;
        float e0 = EQ[qa], e1 = EQ[qa + 8];
#pragma unroll
        for (int jt = 0; jt < 4; jt++) {
            int col = jt * 8 + 2 * kq;
            atomicAdd(&out[qa * 32 + col],           e0 * (zH[mt][jt][0] + zL[mt][jt][0] * 9.765625e-4f));
            atomicAdd(&out[qa * 32 + col + 1],       e0 * (zH[mt][jt][1] + zL[mt][jt][1] * 9.765625e-4f));
            atomicAdd(&out[(qa + 8) * 32 + col],     e1 * (zH[mt][jt][2] + zL[mt][jt][2] * 9.765625e-4f));
            atomicAdd(&out[(qa + 8) * 32 + col + 1], e1 * (zH[mt][jt][3] + zL[mt][jt][3] * 9.765625e-4f));
        }
    }
}

// ---------------- launch ----------------
extern "C" void kernel_launch(void* const* d_in, const int* in_sizes, int n_in,
                              void* d_out, int out_size)
{
    const float* x_mu   = (const float*)d_in[0];
    const float* y_eta  = (const float*)d_in[1];
    const float* y_mean = (const float*)d_in[2];
    const float* y_var  = (const float*)d_in[3];
    const float* X_mean = (const float*)d_in[4];
    const float* X_var  = (const float*)d_in[5];
    const float* Z_mean = (const float*)d_in[6];
    const float* Z_var  = (const float*)d_in[7];
    const float* kXXm   = (const float*)d_in[8];
    const float* kXXv   = (const float*)d_in[9];
    float* out = (float*)d_out;

    const int SMA  = 36864 + 20480 + 2 * 5120;                         // 67584
    const int SMB0 = (128 * 72 + 2 * 64 * 72 + 4 * 32 * 72) * 2;       // 55296
    const int SMB1 = (128 * 104 + 2 * 64 * 104 + 4 * 32 * 72) * 2;     // 71680
    cudaFuncSetAttribute(stageA<0>, cudaFuncAttributeMaxDynamicSharedMemorySize, SMA);
    cudaFuncSetAttribute(stageA<1>, cudaFuncAttributeMaxDynamicSharedMemorySize, SMA);
    cudaFuncSetAttribute(stageB<64, 0>, cudaFuncAttributeMaxDynamicSharedMemorySize, SMB0);
    cudaFuncSetAttribute(stageB<96, 1>, cudaFuncAttributeMaxDynamicSharedMemorySize, SMB1);

    prep_q<<<1024, 256>>>(x_mu, y_eta, y_mean, y_var, out);
    prep_xn<64, 0><<<1024, 256>>>(X_mean);
    prep_xn<96, 1><<<1024, 256>>>(X_var);
    prep_zt<<<1024, 256>>>(Z_mean, Z_var);

    stageA<0><<<dim3(64, 4), 256, SMA>>>(kXXm);
    stageA<1><<<dim3(64, 4), 256, SMA>>>(kXXv);
    scaleL<<<1024, 256>>>();

    stageB<64, 0><<<dim3(64, 4), 256, SMB0>>>(out);
    stageB<96, 1><<<dim3(64, 4), 256, SMB1>>>(out);
}

// round 12
// speedup vs baseline: 5.0973x; 1.0344x over previous
#include <cuda_runtime.h>
#include <cuda_fp16.h>
#include <cstdint>

#define NQ 8192

__device__ __half g_qmh[NQ * 64];
__device__ __half g_qvh[NQ * 96];
__device__ __half g_Xmh[NQ * 64];
__device__ __half g_Xvh[NQ * 96];
__device__ float g_eqm[NQ], g_eqv[NQ], g_exnm[NQ], g_exnv[NQ];
__device__ float g_L[2][NQ * 32];
__device__ __half g_ZTh[2][32 * NQ], g_ZTl[2][32 * NQ];
__device__ __half g_LTh[2][32 * NQ], g_LTl[2][32 * NQ];

__device__ __forceinline__ uint32_t sm_u32(const void* p) {
    uint32_t a;
    asm("{ .reg .u64 t; cvta.to.shared.u64 t, %1; cvt.u32.u64 %0, t; }" : "=r"(a) : "l"(p));
    return a;
}
__device__ __forceinline__ void cp16(uint32_t d, const void* s) {
    asm volatile("cp.async.cg.shared.global [%0], [%1], 16;" :: "r"(d), "l"(s) : "memory");
}
#define CPC() asm volatile("cp.async.commit_group;" ::: "memory")
#define CPW(n) asm volatile("cp.async.wait_group %0;" :: "n"(n) : "memory")

__device__ __forceinline__ void mma16(float* c, const uint32_t* a, const uint32_t* b) {
    asm volatile(
        "mma.sync.aligned.m16n8k16.row.col.f32.f16.f16.f32 "
        "{%0,%1,%2,%3},{%4,%5,%6,%7},{%8,%9},{%0,%1,%2,%3};"
        : "+f"(c[0]), "+f"(c[1]), "+f"(c[2]), "+f"(c[3])
        : "r"(a[0]), "r"(a[1]), "r"(a[2]), "r"(a[3]), "r"(b[0]), "r"(b[1]));
}
#define LDSM4(r, addr) \
    asm volatile("ldmatrix.sync.aligned.m8n8.x4.shared.b16 {%0,%1,%2,%3}, [%4];" \
        : "=r"((r)[0]), "=r"((r)[1]), "=r"((r)[2]), "=r"((r)[3]) : "r"(addr))

__device__ __forceinline__ __half2 splitHi(float x, float y) {
    return __halves2half2(__float2half(x), __float2half(y));
}
__device__ __forceinline__ __half2 splitLo(float x, float y) {
    float hx = __half2float(__float2half(x)), hy = __half2float(__float2half(y));
    return __halves2half2(__float2half((x - hx) * 1024.0f),
                          __float2half((y - hy) * 1024.0f));
}
__device__ __forceinline__ uint32_t packh(float x, float y) {
    __half2 h = __halves2half2(__float2half(x), __float2half(y));
    return *reinterpret_cast<uint32_t*>(&h);
}

// ---------------- fused prep: 4 sections of 1024 blocks ----------------
__global__ __launch_bounds__(256) void prep_all(
    const float* __restrict__ x_mu, const float* __restrict__ y_eta,
    const float* __restrict__ y_mean, const float* __restrict__ y_var,
    const float* __restrict__ X_mean, const float* __restrict__ X_var,
    const float* __restrict__ Zm, const float* __restrict__ Zv,
    float* __restrict__ out)
{
    int sec = blockIdx.x >> 10, bx = blockIdx.x & 1023;
    int lane = threadIdx.x & 31;
    if (sec == 0) {
        int q = bx * 8 + (threadIdx.x >> 5);
        float a = x_mu[q * 32 + lane];
        float s = y_mean[q * 32 + lane] + y_var[q * 32 + lane];
        float e = 0.01f * y_eta[(NQ - 1 - q) * 32 + lane];
        g_qmh[q * 64 + lane] = __float2half(a);
        g_qmh[q * 64 + 32 + lane] = __float2half(s);
        g_qvh[q * 96 + lane] = __float2half(a);
        g_qvh[q * 96 + 32 + lane] = __float2half(e);
        g_qvh[q * 96 + 64 + lane] = __float2half(s);
        out[q * 32 + lane] = s;
        float nm = a * a + s * s, nv = nm + e * e;
#pragma unroll
        for (int o = 16; o > 0; o >>= 1) {
            nm += __shfl_xor_sync(~0u, nm, o);
            nv += __shfl_xor_sync(~0u, nv, o);
        }
        if (lane == 0) {
            g_eqm[q] = __expf(-nm * 0.0078125f);
            g_eqv[q] = __expf(-nv * 0.0078125f);
        }
    } else if (sec == 1) {
        int n = bx * 8 + (threadIdx.x >> 5);
        float acc = 0.0f;
#pragma unroll
        for (int d = 0; d < 64; d += 32) {
            float v = X_mean[(size_t)n * 64 + d + lane];
            g_Xmh[(size_t)n * 64 + d + lane] = __float2half(v);
            acc = fmaf(v, v, acc);
        }
#pragma unroll
        for (int o = 16; o > 0; o >>= 1) acc += __shfl_xor_sync(~0u, acc, o);
        if (lane == 0) g_exnm[n] = __expf(-acc * 0.0078125f);
    } else if (sec == 2) {
        int n = bx * 8 + (threadIdx.x >> 5);
        float acc = 0.0f;
#pragma unroll
        for (int d = 0; d < 96; d += 32) {
            float v = X_var[(size_t)n * 96 + d + lane];
            g_Xvh[(size_t)n * 96 + d + lane] = __float2half(v);
            acc = fmaf(v, v, acc);
        }
#pragma unroll
        for (int o = 16; o > 0; o >>= 1) acc += __shfl_xor_sync(~0u, acc, o);
        if (lane == 0) g_exnv[n] = __expf(-acc * 0.0078125f);
    } else {
        int o = bx * 256 + threadIdx.x;
        int j = o >> 13, n = o & (NQ - 1);
        float zm = Zm[n * 32 + j], zv = Zv[n * 32 + j];
        g_ZTh[0][o] = __low2half(splitHi(zm, zm)); g_ZTl[0][o] = __low2half(splitLo(zm, zm));
        g_ZTh[1][o] = __low2half(splitHi(zv, zv)); g_ZTl[1][o] = __low2half(splitLo(zv, zv));
        g_L[0][o] = 0.0f; g_L[1][o] = 0.0f;
    }
}

__global__ __launch_bounds__(256) void scaleL()
{
    int o = blockIdx.x * 256 + threadIdx.x;
    int j = o >> 13, n = o & (NQ - 1);
    float a = g_L[0][n * 32 + j] * g_exnm[n];
    float b = g_L[1][n * 32 + j] * g_exnv[n];
    g_LTh[0][o] = __low2half(splitHi(a, a)); g_LTl[0][o] = __low2half(splitLo(a, a));
    g_LTh[1][o] = __low2half(splitHi(b, b)); g_LTl[1][o] = __low2half(splitLo(b, b));
}

// ---------------- Stage A: Lambda = kXX_inv @ Z  (fp16 2-term: Ah*(Zh+Zl)) ----------------
// grid (64 row-blocks x 128, 4 k-splits x 2048), block 256, occ 2, 64 chunks of k32.
template <int V>
__global__ __launch_bounds__(256, 2) void stageA(const float* __restrict__ A)
{
    extern __shared__ char smA[];
    float*  sAf = (float*)smA;                           // [2][128*36]
    __half* sAh = (__half*)(smA + 36864);                // [2][128*40]
    __half* sZh = (__half*)(smA + 36864 + 20480);        // [2][32*40]
    __half* sZl = sZh + 2 * 32 * 40;
    int tid = threadIdx.x, wid = tid >> 5, lane = tid & 31;
    int g = lane >> 2, kq = lane & 3;
    size_t r0 = (size_t)blockIdx.x * 128;
    int kb = blockIdx.y * 2048;
    uint32_t aAf = sm_u32(sAf), aZh = sm_u32(sZh), aZl = sm_u32(sZl);

    auto load = [&](int c) {
        int b = c & 1, kc = kb + c * 32;
#pragma unroll
        for (int t = 0; t < 4; t++) {
            int f = tid + 256 * t, r = f >> 3, kg = f & 7;
            cp16(aAf + (b * 128 * 36 + r * 36 + kg * 4) * 4,
                 A + (r0 + r) * NQ + kc + kg * 4);
        }
        {
            int h = tid >> 7, rem = tid & 127, j = rem >> 2, kg = rem & 3;
            const __half* src = h ? g_ZTl[V] : g_ZTh[V];
            cp16((h ? aZl : aZh) + (b * 32 * 40 + j * 40 + kg * 8) * 2,
                 src + (size_t)j * NQ + kc + kg * 8);
        }
        CPC();
    };
    load(0);

    float accH[4][4], accL[4][4];
#pragma unroll
    for (int i = 0; i < 4; i++)
#pragma unroll
        for (int j = 0; j < 4; j++) { accH[i][j] = 0.0f; accL[i][j] = 0.0f; }

    for (int c = 0; c < 64; c++) {
        int b = c & 1;
        if (c + 1 < 64) { load(c + 1); CPW(1); } else CPW(0);
        __syncthreads();
#pragma unroll
        for (int t = 0; t < 8; t++) {
            int idx = tid + 256 * t;
            int r = idx >> 4, kp = idx & 15;
            float2 v = *(float2*)&sAf[b * 128 * 36 + r * 36 + kp * 2];
            *(__half2*)&sAh[b * 128 * 40 + r * 40 + kp * 2] = splitHi(v.x, v.y);
        }
        __syncthreads();
        const __half* pAh = sAh + b * 128 * 40;
        const __half* pZh = sZh + b * 32 * 40;
        const __half* pZl = sZl + b * 32 * 40;
        int rA = wid * 16 + g;
#pragma unroll
        for (int ks = 0; ks < 2; ks++) {
            int ko = ks * 16 + 2 * kq;
            uint32_t ah[4];
            ah[0] = *(const uint32_t*)&pAh[rA * 40 + ko];
            ah[1] = *(const uint32_t*)&pAh[(rA + 8) * 40 + ko];
            ah[2] = *(const uint32_t*)&pAh[rA * 40 + ko + 8];
            ah[3] = *(const uint32_t*)&pAh[(rA + 8) * 40 + ko + 8];
#pragma unroll
            for (int nt = 0; nt < 4; nt++) {
                int rB = nt * 8 + g;
                uint32_t bh[2], bl[2];
                bh[0] = *(const uint32_t*)&pZh[rB * 40 + ko];
                bh[1] = *(const uint32_t*)&pZh[rB * 40 + ko + 8];
                bl[0] = *(const uint32_t*)&pZl[rB * 40 + ko];
                bl[1] = *(const uint32_t*)&pZl[rB * 40 + ko + 8];
                mma16(accH[nt], ah, bh);
                mma16(accL[nt], ah, bl);
            }
        }
        __syncthreads();
    }
    float* L = g_L[V];
    size_t ra = r0 + wid * 16 + g;
#pragma unroll
    for (int nt = 0; nt < 4; nt++) {
        int col = nt * 8 + 2 * kq;
        atomicAdd(&L[ra * 32 + col],           accH[nt][0] + accL[nt][0] * 9.765625e-4f);
        atomicAdd(&L[ra * 32 + col + 1],       accH[nt][1] + accL[nt][1] * 9.765625e-4f);
        atomicAdd(&L[(ra + 8) * 32 + col],     accH[nt][2] + accL[nt][2] * 9.765625e-4f);
        atomicAdd(&L[(ra + 8) * 32 + col + 1], accH[nt][3] + accL[nt][3] * 9.765625e-4f);
    }
}

// ---------------- Stage B: fused RBF + z, K in registers, ldmatrix fragments ----------------
// grid (64 q-tiles x 128, 4 n-splits x 2048), block 256, occ 2, 32 chunks of 64 n.
template <int D, int V>
__global__ __launch_bounds__(256, 2) void stageB(float* __restrict__ out)
{
    const __half* Qg = V ? g_qvh : g_qmh;
    const __half* Xg = V ? g_Xvh : g_Xmh;
    const float*  EQ = V ? g_eqv : g_eqm;
    extern __shared__ __half smB[];
    const int SP = D + 8;
    __half* sQ  = smB;                    // [128][SP]
    __half* sX  = sQ + 128 * SP;          // [2][64][SP]
    __half* sLh = sX + 2 * 64 * SP;       // [2][32 j][72 n]
    __half* sLl = sLh + 2 * 32 * 72;
    uint32_t aQ = sm_u32(sQ), aX = sm_u32(sX), aLh = sm_u32(sLh), aLl = sm_u32(sLl);
    int tid = threadIdx.x, wid = tid >> 5, lane = tid & 31;
    int g = lane >> 2, kq = lane & 3;
    int wm = wid >> 1, wn = wid & 1;
    int q0 = blockIdx.x * 128, nb = blockIdx.y * 2048;
    const int NC = 32;
    const int XB = 64 * SP * 2, LB = 32 * 72 * 2;

    // per-lane ldmatrix row addresses (m = lane>>3 selects the 8x8 submatrix)
    int m = lane >> 3, lr = lane & 7;
    uint32_t adrQ[2], adrX[2], adrLh[2], adrLl[2];
#pragma unroll
    for (int mt = 0; mt < 2; mt++) {
        int row = wm * 32 + mt * 16 + (m & 1) * 8 + lr;
        adrQ[mt] = aQ + (row * SP) * 2 + (m >> 1) * 16;
    }
#pragma unroll
    for (int p = 0; p < 2; p++) {
        int n = wn * 32 + (2 * p + (m >> 1)) * 8 + lr;
        adrX[p] = aX + (n * SP) * 2 + (m & 1) * 16;
        int j = (2 * p + (m >> 1)) * 8 + lr;
        uint32_t off = (j * 72) * 2 + wn * 64 + (m & 1) * 16;
        adrLh[p] = aLh + off;
        adrLl[p] = aLl + off;
    }

    for (int idx = tid; idx < 128 * (D / 8); idx += 256) {
        int r = idx / (D / 8), kg = idx % (D / 8);
        cp16(aQ + (r * SP + kg * 8) * 2, Qg + (size_t)(q0 + r) * D + kg * 8);
    }
    auto loadC = [&](int c) {
        int b = c & 1, n0 = nb + c * 64;
        for (int idx = tid; idx < 64 * (D / 8); idx += 256) {
            int r = idx / (D / 8), kg = idx % (D / 8);
            cp16(aX + b * XB + (r * SP + kg * 8) * 2,
                 Xg + (size_t)(n0 + r) * D + kg * 8);
        }
#pragma unroll
        for (int t = 0; t < 2; t++) {
            int f = tid + 256 * t;
            int h = f >> 8, rem = f & 255, j = rem >> 3, kg = rem & 7;
            const __half* src = h ? g_LTl[V] : g_LTh[V];
            cp16((h ? aLl : aLh) + b * LB + (j * 72 + kg * 8) * 2,
                 src + (size_t)j * NQ + n0 + kg * 8);
        }
        CPC();
    };
    loadC(0);

    float zH[2][4][4], zL[2][4][4];
#pragma unroll
    for (int mm = 0; mm < 2; mm++)
#pragma unroll
        for (int i = 0; i < 4; i++)
#pragma unroll
            for (int j = 0; j < 4; j++) { zH[mm][i][j] = 0.0f; zL[mm][i][j] = 0.0f; }

    for (int c = 0; c < NC; c++) {
        int b = c & 1;
        if (c + 1 < NC) { loadC(c + 1); CPW(1); } else CPW(0);
        __syncthreads();

        // mma1: S = Q . X^T for this warp's 32q x 32n tile
        float s[2][4][4];
#pragma unroll
        for (int mt = 0; mt < 2; mt++)
#pragma unroll
            for (int nt = 0; nt < 4; nt++)
#pragma unroll
                for (int i = 0; i < 4; i++) s[mt][nt][i] = 0.0f;
#pragma unroll
        for (int ks = 0; ks < D / 16; ks++) {
            uint32_t a2[2][4], bb[2][4];
            LDSM4(a2[0], adrQ[0] + ks * 32);
            LDSM4(a2[1], adrQ[1] + ks * 32);
            LDSM4(bb[0], adrX[0] + b * XB + ks * 32);
            LDSM4(bb[1], adrX[1] + b * XB + ks * 32);
#pragma unroll
            for (int p = 0; p < 2; p++) {
                mma16(s[0][2 * p],     a2[0], &bb[p][0]);
                mma16(s[0][2 * p + 1], a2[0], &bb[p][2]);
                mma16(s[1][2 * p],     a2[1], &bb[p][0]);
                mma16(s[1][2 * p + 1], a2[1], &bb[p][2]);
            }
        }
        // K = exp(S/64) packed directly into mma2 A-fragments (k = n dim)
        uint32_t ka[2][2][4];
#pragma unroll
        for (int mt = 0; mt < 2; mt++)
#pragma unroll
            for (int nt = 0; nt < 4; nt++)
#pragma unroll
                for (int i = 0; i < 4; i++)
                    s[mt][nt][i] = __expf(s[mt][nt][i] * 0.015625f);
#pragma unroll
        for (int mt = 0; mt < 2; mt++)
#pragma unroll
            for (int ks = 0; ks < 2; ks++) {
                ka[mt][ks][0] = packh(s[mt][2 * ks][0],     s[mt][2 * ks][1]);
                ka[mt][ks][1] = packh(s[mt][2 * ks][2],     s[mt][2 * ks][3]);
                ka[mt][ks][2] = packh(s[mt][2 * ks + 1][0], s[mt][2 * ks + 1][1]);
                ka[mt][ks][3] = packh(s[mt][2 * ks + 1][2], s[mt][2 * ks + 1][3]);
            }

        // mma2: z += K . Lam'^T over this warp's 32-n slice
#pragma unroll
        for (int ks = 0; ks < 2; ks++) {
            uint32_t bh[2][4], bl[2][4];
            LDSM4(bh[0], adrLh[0] + b * LB + ks * 32);
            LDSM4(bh[1], adrLh[1] + b * LB + ks * 32);
            LDSM4(bl[0], adrLl[0] + b * LB + ks * 32);
            LDSM4(bl[1], adrLl[1] + b * LB + ks * 32);
#pragma unroll
            for (int jt = 0; jt < 4; jt++) {
                int jp = jt >> 1, ji = (jt & 1) * 2;
                mma16(zH[0][jt], ka[0][ks], &bh[jp][ji]);
                mma16(zL[0][jt], ka[0][ks], &bl[jp][ji]);
                mma16(zH[1][jt], ka[1][ks], &bh[jp][ji]);
                mma16(zL[1][jt], ka[1][ks], &bl[jp][ji]);
            }
        }
        __syncthreads();
    }
#pragma unroll
    for (int mt = 0; mt < 2; mt++) {
        int qa = q0 + wm * 32 + mt * 16 + g;
        float e0 = EQ[qa], e1 = EQ[qa + 8];
#pragma unroll
        for (int jt = 0; jt < 4; jt++) {
            int col = jt * 8 + 2 * kq;
            atomicAdd(&out[qa * 32 + col],           e0 * (zH[mt][jt][0] + zL[mt][jt][0] * 9.765625e-4f));
            atomicAdd(&out[qa * 32 + col + 1],       e0 * (zH[mt][jt][1] + zL[mt][jt][1] * 9.765625e-4f));
            atomicAdd(&out[(qa + 8) * 32 + col],     e1 * (zH[mt][jt][2] + zL[mt][jt][2] * 9.765625e-4f));
            atomicAdd(&out[(qa + 8) * 32 + col + 1], e1 * (zH[mt][jt][3] + zL[mt][jt][3] * 9.765625e-4f));
        }
    }
}

// ---------------- launch ----------------
extern "C" void kernel_launch(void* const* d_in, const int* in_sizes, int n_in,
                              void* d_out, int out_size)
{
    const float* x_mu   = (const float*)d_in[0];
    const float* y_eta  = (const float*)d_in[1];
    const float* y_mean = (const float*)d_in[2];
    const float* y_var  = (const float*)d_in[3];
    const float* X_mean = (const float*)d_in[4];
    const float* X_var  = (const float*)d_in[5];
    const float* Z_mean = (const float*)d_in[6];
    const float* Z_var  = (const float*)d_in[7];
    const float* kXXm   = (const float*)d_in[8];
    const float* kXXv   = (const float*)d_in[9];
    float* out = (float*)d_out;

    const int SMA  = 36864 + 20480 + 2 * 5120;                         // 67584
    const int SMB0 = (128 * 72 + 2 * 64 * 72 + 4 * 32 * 72) * 2;       // 55296
    const int SMB1 = (128 * 104 + 2 * 64 * 104 + 4 * 32 * 72) * 2;     // 71680
    cudaFuncSetAttribute(stageA<0>, cudaFuncAttributeMaxDynamicSharedMemorySize, SMA);
    cudaFuncSetAttribute(stageA<1>, cudaFuncAttributeMaxDynamicSharedMemorySize, SMA);
    cudaFuncSetAttribute(stageB<64, 0>, cudaFuncAttributeMaxDynamicSharedMemorySize, SMB0);
    cudaFuncSetAttribute(stageB<96, 1>, cudaFuncAttributeMaxDynamicSharedMemorySize, SMB1);

    prep_all<<<4096, 256>>>(x_mu, y_eta, y_mean, y_var, X_mean, X_var,
                            Z_mean, Z_var, out);

    stageA<0><<<dim3(64, 4), 256, SMA>>>(kXXm);
    stageA<1><<<dim3(64, 4), 256, SMA>>>(kXXv);
    scaleL<<<1024, 256>>>();

    stageB<64, 0><<<dim3(64, 4), 256, SMB0>>>(out);
    stageB<96, 1><<<dim3(64, 4), 256, SMB1>>>(out);
}